// round 13
// baseline (speedup 1.0000x reference)
#include <cuda_runtime.h>
#include <cuda_fp16.h>
#include <cstdint>

#define S_  2048
#define N_  8
#define E_  512
#define C_  1024
#define G_  32
#define CG_ 32
#define M_  (S_ * N_)        // 16384 tokens
#define R_  (M_ + C_)        // 17408 rows (x rows then W1 rows)
#define TAU_ 6e-3f

// ---------------- scratch (no allocations allowed) ----------------
__device__ __half g_h1[(size_t)R_ * E_];     // fp16 [x ; 64*W1]
__device__ __half g_W2h[(size_t)C_ * E_];    // fp16 W2 transposed [c][e]
__device__ unsigned g_idx[(size_t)M_ * G_];  // packed (a1 | a2<<8 | ui<<16)

// ---------------- PTX helpers (base sm_103 legal) ----------------
__device__ __forceinline__ uint32_t smem_u32(const void* p) {
    uint32_t a;
    asm("{ .reg .u64 t; cvta.to.shared.u64 t, %1; cvt.u32.u64 %0, t; }"
        : "=r"(a) : "l"(p));
    return a;
}
__device__ __forceinline__ void ldsm_x4(uint32_t& r0, uint32_t& r1,
                                        uint32_t& r2, uint32_t& r3, uint32_t addr) {
    asm volatile("ldmatrix.sync.aligned.m8n8.x4.shared.b16 {%0,%1,%2,%3}, [%4];"
                 : "=r"(r0), "=r"(r1), "=r"(r2), "=r"(r3) : "r"(addr));
}
__device__ __forceinline__ void mma16816(float* d, const uint32_t* a, const uint32_t* b) {
    asm volatile(
        "mma.sync.aligned.m16n8k16.row.col.f32.f16.f16.f32 "
        "{%0,%1,%2,%3},{%4,%5,%6,%7},{%8,%9},{%0,%1,%2,%3};"
        : "+f"(d[0]), "+f"(d[1]), "+f"(d[2]), "+f"(d[3])
        : "r"(a[0]), "r"(a[1]), "r"(a[2]), "r"(a[3]), "r"(b[0]), "r"(b[1]));
}
#define CP16(dst, src) \
    asm volatile("cp.async.cg.shared.global [%0], [%1], 16;" :: "r"(dst), "l"(src))
#define CP_COMMIT() asm volatile("cp.async.commit_group;" ::: "memory")

// ---------------- kernel 1: merged prep (split + W2 transpose) --------------
// blocks [0, 4352): fp32 -> fp16 of [x ; 64*W1]
// blocks [4352, 4864): transpose W2 (E,C) -> fp16 W2T (C,E), 32x32 tiles
#define SPLIT_BLOCKS ((int)(((size_t)R_ * E_) / 8 / 256))   // 4352
__global__ __launch_bounds__(256)
void prep_kernel(const float* __restrict__ x, const float* __restrict__ W1,
                 const float* __restrict__ W2) {
    __shared__ float tile[32][33];
    const int bid = blockIdx.x;
    const int tid = threadIdx.x;
    if (bid < SPLIT_BLOCKS) {
        const size_t i = ((size_t)bid * 256 + tid) * 8;
        const size_t r = i >> 9;
        const float sc = (r < (size_t)M_) ? 1.0f : 64.0f;
        const float* src = (r < (size_t)M_) ? (x + i) : (W1 + (i - (size_t)M_ * E_));
        const float4 a = ((const float4*)src)[0];
        const float4 b = ((const float4*)src)[1];
        float v[8] = {a.x, a.y, a.z, a.w, b.x, b.y, b.z, b.w};
        __align__(16) __half h1[8];
#pragma unroll
        for (int e = 0; e < 8; e++) h1[e] = __float2half_rn(v[e] * sc);
        *reinterpret_cast<uint4*>(&g_h1[i]) = *reinterpret_cast<const uint4*>(h1);
    } else {
        const int b  = bid - SPLIT_BLOCKS;
        const int c0 = (b & 31) * 32;
        const int e0 = (b >> 5) * 32;
        const int tx = tid & 31, ty = tid >> 5;   // 32 x 8
#pragma unroll
        for (int r = 0; r < 32; r += 8)
            tile[ty + r][tx] = W2[(size_t)(e0 + ty + r) * C_ + c0 + tx];
        __syncthreads();
#pragma unroll
        for (int r = 0; r < 32; r += 8)
            g_W2h[(size_t)(c0 + ty + r) * E_ + e0 + tx] =
                __float2half_rn(tile[tx][ty + r]);
    }
}

// exact-rescue dot — VALIDATED arithmetic (R4/R6/R9-R12): ONE sequential fp32
// fmaf chain, k ascending, float4 loads. DO NOT reorder or split.
__device__ __forceinline__ float exact_logit(const float* __restrict__ xr,
                                             const float* __restrict__ wr,
                                             float cbv) {
    float acc = 0.0f;
#pragma unroll 8
    for (int k = 0; k < E_; k += 4) {
        const float4 xv = *(const float4*)(xr + k);
        const float4 wv = *(const float4*)(wr + k);
        acc = fmaf(xv.x, wv.x, acc);
        acc = fmaf(xv.y, wv.y, acc);
        acc = fmaf(xv.z, wv.z, acc);
        acc = fmaf(xv.w, wv.w, acc);
    }
    return fmaf(3.0f, acc, cbv);
}

// warp-collective rescue (VALIDATED R11/R12 form): lane i = candidate class i,
// warp argmax with lowest-index tie-break == sequential strict-> first max.
// __noinline__ firewalls register pressure away from the GEMM mainloop.
__device__ __noinline__ void warp_rescue(unsigned bm1, unsigned bm2, int bpair,
                                         int bg4, int bn,
                                         const float* __restrict__ xr,
                                         const float* __restrict__ W1g,
                                         const float* __restrict__ cbp,
                                         const float* __restrict__ g1,
                                         const float* __restrict__ g2,
                                         int lane, int* o1, int* o2) {
    const bool need1 = (bm1 >> lane) & 1u;
    const bool need2 = (bm2 >> lane) & 1u;
    float cand1 = -3.4e38f, cand2 = -3.4e38f;
    if (need1 || need2) {
        const float cbv = cbp[bg4 * 32 + lane];
        const float vex = exact_logit(
            xr, W1g + (size_t)(bn + bg4 * 32 + lane) * E_, cbv);
        if (need1) cand1 = vex + g1[(size_t)bpair * CG_ + lane];
        if (need2) cand2 = vex + g2[(size_t)bpair * CG_ + lane];
    }
    int i1 = lane, i2 = lane;
#pragma unroll
    for (int off = 16; off > 0; off >>= 1) {
        const float ov1 = __shfl_xor_sync(0xFFFFFFFFu, cand1, off);
        const int   oi1 = __shfl_xor_sync(0xFFFFFFFFu, i1, off);
        if (ov1 > cand1 || (ov1 == cand1 && oi1 < i1)) { cand1 = ov1; i1 = oi1; }
        const float ov2 = __shfl_xor_sync(0xFFFFFFFFu, cand2, off);
        const int   oi2 = __shfl_xor_sync(0xFFFFFFFFu, i2, off);
        if (ov2 > cand2 || (ov2 == cand2 && oi2 < i2)) { cand2 = ov2; i2 = oi2; }
    }
    *o1 = i1;
    *o2 = i2;
}

// ---------------- kernel 2: fp16 mma.sync GEMM + fused softmax/sample -------
// Tile: BM=128, BN=128, BK=32, 3-stage. smem/stage: A (128x80B) + B (128x80B)
#define A_SZ      10240
#define STAGE_SZ  (2 * A_SZ)                // 20480
#define CS        132                       // C smem stride (floats)
#define SMEM_BYTES (128 * CS * 4)           // 67584 (>= 3*STAGE_SZ = 61440)
#define NST       (E_ / 32)                 // 16
#define SCALE_    (3.0f / 64.0f)

__device__ __forceinline__ void load_stage(uint32_t sb, int tid, int bm, int bn,
                                           int s, int buf) {
    const uint32_t stage = sb + buf * STAGE_SZ;
    const size_t kofs = (size_t)s * 32;
#pragma unroll
    for (int it = 0; it < 2; it++) {
        const int o = tid + it * 256;           // 0..511 -> 128 rows x 4 chunks
        const int row = o >> 2, ch = o & 3;
        const uint32_t dst = row * 80 + ch * 16;
        CP16(stage + dst,        g_h1 + (size_t)(bm + row) * E_ + kofs + ch * 8);
        CP16(stage + A_SZ + dst, g_h1 + (size_t)(M_ + bn + row) * E_ + kofs + ch * 8);
    }
}

__global__ __launch_bounds__(256, 2)
void gemm_fused_kernel(const float* __restrict__ xg,
                       const float* __restrict__ W1g,
                       const float* __restrict__ b1,
                       const float* __restrict__ coff,
                       const float* __restrict__ g1,
                       const float* __restrict__ g2,
                       const float* __restrict__ w_interp,
                       const float* __restrict__ u_interp,
                       float* __restrict__ outSampled,
                       float* __restrict__ outSoft) {
    extern __shared__ char smem[];
    __shared__ float cb[128];
    const int tid  = threadIdx.x;
    const int lane = tid & 31;
    const int wid  = tid >> 5;
    const int bn   = blockIdx.x * 128;
    const int bm   = blockIdx.y * 128;
    const uint32_t sb = smem_u32(smem);

    if (tid < 128) cb[tid] = 3.0f * b1[bn + tid] + coff[bn + tid];

    // warp tiling: 2 (m) x 4 (n); warp tile m64 x n32
    const int m0 = (wid >> 2) * 64;
    const int n0 = (wid & 3) * 32;
    const int lrow = lane & 7;
    const int lmat = lane >> 3;

    float acc[4][4][4];
#pragma unroll
    for (int i = 0; i < 4; i++)
#pragma unroll
        for (int j = 0; j < 4; j++)
#pragma unroll
            for (int k = 0; k < 4; k++) acc[i][j][k] = 0.0f;

    load_stage(sb, tid, bm, bn, 0, 0); CP_COMMIT();
    load_stage(sb, tid, bm, bn, 1, 1); CP_COMMIT();

#pragma unroll 1
    for (int s = 0; s < NST; s++) {
        if (s + 2 < NST) { load_stage(sb, tid, bm, bn, s + 2, (s + 2) % 3); CP_COMMIT(); }
        if      (s < NST - 2) asm volatile("cp.async.wait_group 2;" ::: "memory");
        else if (s < NST - 1) asm volatile("cp.async.wait_group 1;" ::: "memory");
        else                  asm volatile("cp.async.wait_group 0;" ::: "memory");
        __syncthreads();

        const uint32_t stage = sb + (s % 3) * STAGE_SZ;
        const uint32_t A1 = stage;
        const uint32_t B1 = stage + A_SZ;

#pragma unroll
        for (int kk = 0; kk < 32; kk += 16) {
            uint32_t a1f[4][4], b1f[8];
#pragma unroll
            for (int mt = 0; mt < 4; mt++) {
                const int row = m0 + mt * 16 + (lmat & 1) * 8 + lrow;
                const int col = kk + (lmat >> 1) * 8;
                const uint32_t off = row * 80 + col * 2;
                ldsm_x4(a1f[mt][0], a1f[mt][1], a1f[mt][2], a1f[mt][3], A1 + off);
            }
#pragma unroll
            for (int j = 0; j < 2; j++) {
                const int row = n0 + j * 16 + (lmat >> 1) * 8 + lrow;
                const int col = kk + (lmat & 1) * 8;
                const uint32_t off = row * 80 + col * 2;
                ldsm_x4(b1f[j*4+0], b1f[j*4+1], b1f[j*4+2], b1f[j*4+3], B1 + off);
            }
#pragma unroll
            for (int mt = 0; mt < 4; mt++)
#pragma unroll
                for (int nt = 0; nt < 4; nt++) {
                    const int bb = (nt >> 1) * 4 + (nt & 1) * 2;
                    mma16816(acc[mt][nt], a1f[mt], &b1f[bb]);
                }
        }
        __syncthreads();
    }

    // ------- write accums to smem C (reuse stage memory) -------
    float* Cs = (float*)smem;
    const int crow = lane >> 2;
    const int ccol = (lane & 3) * 2;
#pragma unroll
    for (int mt = 0; mt < 4; mt++)
#pragma unroll
        for (int nt = 0; nt < 4; nt++) {
            const int r = m0 + mt * 16 + crow;
            const int c = n0 + nt * 8 + ccol;
            *(float2*)&Cs[(size_t)r * CS + c]       = make_float2(acc[mt][nt][0], acc[mt][nt][1]);
            *(float2*)&Cs[(size_t)(r + 8) * CS + c] = make_float2(acc[mt][nt][2], acc[mt][nt][3]);
        }
    __syncthreads();

    // ------- fused epilogue: softmax + sample + warp-collective rescue -------
#pragma unroll 1
    for (int rep = 0; rep < 2; rep++) {
        const int p  = rep * 256 + tid;     // 0..511
        const int tl = p >> 2;              // token local 0..127
        const int g4 = p & 3;               // group within block 0..3
        const int token = bm + tl;
        const float* cp = &Cs[(size_t)tl * CS + g4 * 32];

        float v[32];
#pragma unroll
        for (int q = 0; q < 8; q++) {
            const float4 c4 = *(const float4*)(cp + q * 4);
            v[q*4+0] = SCALE_ * c4.x + cb[g4*32 + q*4+0];
            v[q*4+1] = SCALE_ * c4.y + cb[g4*32 + q*4+1];
            v[q*4+2] = SCALE_ * c4.z + cb[g4*32 + q*4+2];
            v[q*4+3] = SCALE_ * c4.w + cb[g4*32 + q*4+3];
        }

        float mx = v[0];
#pragma unroll
        for (int i = 1; i < 32; i++) mx = fmaxf(mx, v[i]);
        float e[32], sum = 0.0f;
#pragma unroll
        for (int i = 0; i < 32; i++) { e[i] = __expf(v[i] - mx); sum += e[i]; }
        const float inv = 1.0f / sum;

        float* so = outSoft + (size_t)token * C_ + bn + g4 * 32;
#pragma unroll
        for (int q = 0; q < 8; q++)
            *(float4*)(so + q * 4) = make_float4(e[q*4+0]*inv, e[q*4+1]*inv,
                                                 e[q*4+2]*inv, e[q*4+3]*inv);

        const int gid = (bn >> 5) + g4;
        const int pair = token * G_ + gid;
        const size_t gbase = (size_t)pair * CG_;
        const float* gp1 = g1 + gbase;
        const float* gp2 = g2 + gbase;

        int a1 = 0; float t11 = -3.4e38f, t12 = -3.4e38f;
#pragma unroll
        for (int q = 0; q < 8; q++) {
            const float4 gg = *(const float4*)(gp1 + q * 4);
            const float cc[4] = {v[q*4+0] + gg.x, v[q*4+1] + gg.y,
                                 v[q*4+2] + gg.z, v[q*4+3] + gg.w};
#pragma unroll
            for (int k = 0; k < 4; k++) {
                if (cc[k] > t11) { t12 = t11; t11 = cc[k]; a1 = q*4+k; }
                else if (cc[k] > t12) { t12 = cc[k]; }
            }
        }
        int a2 = 0; float t21 = -3.4e38f, t22 = -3.4e38f;
#pragma unroll
        for (int q = 0; q < 8; q++) {
            const float4 gg = *(const float4*)(gp2 + q * 4);
            const float cc[4] = {v[q*4+0] + gg.x, v[q*4+1] + gg.y,
                                 v[q*4+2] + gg.z, v[q*4+3] + gg.w};
#pragma unroll
            for (int k = 0; k < 4; k++) {
                if (cc[k] > t21) { t22 = t21; t21 = cc[k]; a2 = q*4+k; }
                else if (cc[k] > t22) { t22 = cc[k]; }
            }
        }

        // ---- rescue screen (identical to validated versions) ----
        unsigned m1 = 0, m2 = 0;
        if (t11 - t12 < TAU_) {
            const float thr = t11 - 2.0f * TAU_;
#pragma unroll
            for (int i = 0; i < 32; i++)
                if (v[i] + gp1[i] >= thr) m1 |= (1u << i);
        }
        if (t21 - t22 < TAU_) {
            const float thr = t21 - 2.0f * TAU_;
#pragma unroll
            for (int i = 0; i < 32; i++)
                if (v[i] + gp2[i] >= thr) m2 |= (1u << i);
        }

        // ---- warp-collective rescues, hidden by co-resident warps ----
        unsigned ballot = __ballot_sync(0xFFFFFFFFu, (m1 | m2) != 0u);
        while (ballot) {
            const int src = __ffs(ballot) - 1;
            ballot &= ballot - 1;
            const unsigned bm1 = __shfl_sync(0xFFFFFFFFu, m1, src);
            const unsigned bm2 = __shfl_sync(0xFFFFFFFFu, m2, src);
            const int bpair = __shfl_sync(0xFFFFFFFFu, pair, src);
            const int btok  = __shfl_sync(0xFFFFFFFFu, token, src);
            const int bg4   = __shfl_sync(0xFFFFFFFFu, g4, src);
            int i1, i2;
            warp_rescue(bm1, bm2, bpair, bg4, bn,
                        xg + (size_t)btok * E_, W1g, cb, g1, g2, lane, &i1, &i2);
            if (lane == src) {
                if (bm1) a1 = i1;
                if (bm2) a2 = i2;
            }
        }

        const float w  = w_interp[pair];
        const float u  = u_interp[pair];
        const bool  ui = (u < 1.0f);              // INTERP_PROB = 1.0
        const float wa = ui ? w : 1.0f;
        const float wb = ui ? (1.0f - w) : 0.0f;

        float* sp = outSampled + (size_t)token * C_ + bn + g4 * 32;
#pragma unroll
        for (int q = 0; q < 8; q++) {
            float o[4];
#pragma unroll
            for (int k = 0; k < 4; k++) {
                const int i = q * 4 + k;
                float val = 0.0f;
                if (i == a1) val += wa;
                if (i == a2) val += wb;
                o[k] = val;
            }
            *(float4*)(sp + q * 4) = make_float4(o[0], o[1], o[2], o[3]);
        }
        g_idx[pair] = (unsigned)a1 | ((unsigned)a2 << 8) | (ui ? 0x10000u : 0u);
    }
}

// ---------------- kernel 3: sparse projection (fp16 W2T) + LayerNorm --------
__global__ __launch_bounds__(128)
void proj_ln_kernel(const float* __restrict__ w_interp,
                    const float* __restrict__ b2,
                    const float* __restrict__ gamma,
                    const float* __restrict__ beta,
                    float* __restrict__ outPos,
                    float* __restrict__ outNeg) {
    const int tok = blockIdx.x;
    const int tid = threadIdx.x;   // 128 threads, 4 e's each
    __shared__ unsigned sidx[32];
    __shared__ float    sw[32];
    __shared__ float    red1[4], red2[4];

    if (tid < 32) {
        sidx[tid] = g_idx[(size_t)tok * G_ + tid];
        sw[tid]   = w_interp[(size_t)tok * G_ + tid];
    }
    __syncthreads();

    const int e4 = tid * 4;
    float4 bb = *(const float4*)(b2 + e4);
    float hx = bb.x, hy = bb.y, hz = bb.z, hw = bb.w;

#pragma unroll
    for (int g = 0; g < 32; g++) {
        const unsigned p = sidx[g];
        const float w = sw[g];
        const bool ui = (p & 0x10000u) != 0u;
        const int a1 = p & 255;
        const int a2 = (p >> 8) & 255;
        const float wa = ui ? w : 1.0f;
        const float wb = ui ? (1.0f - w) : 0.0f;
        const uint2 u1 = *(const uint2*)&g_W2h[(size_t)(g * CG_ + a1) * E_ + e4];
        const uint2 u2 = *(const uint2*)&g_W2h[(size_t)(g * CG_ + a2) * E_ + e4];
        const float2 r1a = __half22float2(*(const __half2*)&u1.x);
        const float2 r1b = __half22float2(*(const __half2*)&u1.y);
        const float2 r2a = __half22float2(*(const __half2*)&u2.x);
        const float2 r2b = __half22float2(*(const __half2*)&u2.y);
        hx += wa * r1a.x + wb * r2a.x;
        hy += wa * r1a.y + wb * r2a.y;
        hz += wa * r1b.x + wb * r2b.x;
        hw += wa * r1b.y + wb * r2b.y;
    }

    float s1 = hx + hy + hz + hw;
    float s2 = hx * hx + hy * hy + hz * hz + hw * hw;
#pragma unroll
    for (int off = 16; off > 0; off >>= 1) {
        s1 += __shfl_xor_sync(0xFFFFFFFFu, s1, off);
        s2 += __shfl_xor_sync(0xFFFFFFFFu, s2, off);
    }
    const int wid = tid >> 5, lid = tid & 31;
    if (lid == 0) { red1[wid] = s1; red2[wid] = s2; }
    __syncthreads();
    s1 = red1[0] + red1[1] + red1[2] + red1[3];
    s2 = red2[0] + red2[1] + red2[2] + red2[3];

    const float mean = s1 * (1.0f / (float)E_);
    const float var  = s2 * (1.0f / (float)E_) - mean * mean;
    const float rstd = rsqrtf(var + 1e-5f);

    const float4 gm = *(const float4*)(gamma + e4);
    const float4 bt = *(const float4*)(beta + e4);
    float4 o;
    o.x = (hx - mean) * rstd * gm.x + bt.x;
    o.y = (hy - mean) * rstd * gm.y + bt.y;
    o.z = (hz - mean) * rstd * gm.z + bt.z;
    o.w = (hw - mean) * rstd * gm.w + bt.w;

    *(float4*)(outPos + (size_t)tok * E_ + e4) = o;
    *(float4*)(outNeg + (size_t)tok * E_ + e4) = o;   // rev fwd == sampled
}

// ---------------- launch ----------------
extern "C" void kernel_launch(void* const* d_in, const int* in_sizes, int n_in,
                              void* d_out, int out_size) {
    const float* x     = (const float*)d_in[0];
    const float* W1    = (const float*)d_in[1];
    const float* b1    = (const float*)d_in[2];
    const float* coff  = (const float*)d_in[3];
    const float* W2    = (const float*)d_in[4];
    const float* b2    = (const float*)d_in[5];
    const float* gamma = (const float*)d_in[6];
    const float* beta  = (const float*)d_in[7];
    const float* g1    = (const float*)d_in[8];
    const float* g2    = (const float*)d_in[9];
    const float* wi    = (const float*)d_in[10];
    const float* ui    = (const float*)d_in[11];

    float* out        = (float*)d_out;
    float* outSampled = out;
    float* outSoft    = out + (size_t)M_ * C_;
    float* outPos     = out + 2 * (size_t)M_ * C_;
    float* outNeg     = outPos + (size_t)M_ * E_;

    cudaFuncSetAttribute(gemm_fused_kernel,
                         cudaFuncAttributeMaxDynamicSharedMemorySize, SMEM_BYTES);

    prep_kernel<<<SPLIT_BLOCKS + 512, 256>>>(x, W1, W2);
    gemm_fused_kernel<<<dim3(C_ / 128, M_ / 128), 256, SMEM_BYTES>>>(
        x, W1, b1, coff, g1, g2, wi, ui, outSampled, outSoft);
    proj_ln_kernel<<<M_, 128>>>(wi, b2, gamma, beta, outPos, outNeg);
}

// round 14
// speedup vs baseline: 1.1718x; 1.1718x over previous
#include <cuda_runtime.h>
#include <cuda_fp16.h>
#include <cstdint>

#define S_  2048
#define N_  8
#define E_  512
#define C_  1024
#define G_  32
#define CG_ 32
#define M_  (S_ * N_)        // 16384 tokens
#define R_  (M_ + C_)        // 17408 rows (x rows then W1 rows)
#define TAU_ 6e-3f

// ---------------- scratch (no allocations allowed) ----------------
__device__ __half g_h1[(size_t)R_ * E_];     // fp16 [x ; 64*W1]
__device__ __half g_W2h[(size_t)C_ * E_];    // fp16 W2 transposed [c][e]
__device__ unsigned g_idx[(size_t)M_ * G_];  // packed (a1 | a2<<8 | ui<<16)
__device__ unsigned g_rmask[M_];             // per-token rescue group bitmask
__device__ unsigned g_m1[(size_t)M_ * G_];   // candidate mask draw 1 (valid iff rmask bit)
__device__ unsigned g_m2[(size_t)M_ * G_];   // candidate mask draw 2

// ---------------- PTX helpers (base sm_103 legal) ----------------
__device__ __forceinline__ uint32_t smem_u32(const void* p) {
    uint32_t a;
    asm("{ .reg .u64 t; cvta.to.shared.u64 t, %1; cvt.u32.u64 %0, t; }"
        : "=r"(a) : "l"(p));
    return a;
}
__device__ __forceinline__ void ldsm_x4(uint32_t& r0, uint32_t& r1,
                                        uint32_t& r2, uint32_t& r3, uint32_t addr) {
    asm volatile("ldmatrix.sync.aligned.m8n8.x4.shared.b16 {%0,%1,%2,%3}, [%4];"
                 : "=r"(r0), "=r"(r1), "=r"(r2), "=r"(r3) : "r"(addr));
}
__device__ __forceinline__ void mma16816(float* d, const uint32_t* a, const uint32_t* b) {
    asm volatile(
        "mma.sync.aligned.m16n8k16.row.col.f32.f16.f16.f32 "
        "{%0,%1,%2,%3},{%4,%5,%6,%7},{%8,%9},{%0,%1,%2,%3};"
        : "+f"(d[0]), "+f"(d[1]), "+f"(d[2]), "+f"(d[3])
        : "r"(a[0]), "r"(a[1]), "r"(a[2]), "r"(a[3]), "r"(b[0]), "r"(b[1]));
}
#define CP16(dst, src) \
    asm volatile("cp.async.cg.shared.global [%0], [%1], 16;" :: "r"(dst), "l"(src))
#define CP_COMMIT() asm volatile("cp.async.commit_group;" ::: "memory")

// ---------------- kernel 1: merged prep (split + W2 transpose + rmask zero) -
// blocks [0, 4352): fp32 -> fp16 of [x ; 64*W1]
// blocks [4352, 4864): transpose W2 (E,C) -> fp16 W2T (C,E), 32x32 tiles
#define SPLIT_BLOCKS ((int)(((size_t)R_ * E_) / 8 / 256))   // 4352
__global__ __launch_bounds__(256)
void prep_kernel(const float* __restrict__ x, const float* __restrict__ W1,
                 const float* __restrict__ W2) {
    __shared__ float tile[32][33];
    const int bid = blockIdx.x;
    const int tid = threadIdx.x;
    const int gt = bid * 256 + tid;
    if (gt < M_) g_rmask[gt] = 0u;           // zero rescue masks every launch
    if (bid < SPLIT_BLOCKS) {
        const size_t i = ((size_t)bid * 256 + tid) * 8;
        const size_t r = i >> 9;
        const float sc = (r < (size_t)M_) ? 1.0f : 64.0f;
        const float* src = (r < (size_t)M_) ? (x + i) : (W1 + (i - (size_t)M_ * E_));
        const float4 a = ((const float4*)src)[0];
        const float4 b = ((const float4*)src)[1];
        float v[8] = {a.x, a.y, a.z, a.w, b.x, b.y, b.z, b.w};
        __align__(16) __half h1[8];
#pragma unroll
        for (int e = 0; e < 8; e++) h1[e] = __float2half_rn(v[e] * sc);
        *reinterpret_cast<uint4*>(&g_h1[i]) = *reinterpret_cast<const uint4*>(h1);
    } else {
        const int b  = bid - SPLIT_BLOCKS;
        const int c0 = (b & 31) * 32;
        const int e0 = (b >> 5) * 32;
        const int tx = tid & 31, ty = tid >> 5;   // 32 x 8
#pragma unroll
        for (int r = 0; r < 32; r += 8)
            tile[ty + r][tx] = W2[(size_t)(e0 + ty + r) * C_ + c0 + tx];
        __syncthreads();
#pragma unroll
        for (int r = 0; r < 32; r += 8)
            g_W2h[(size_t)(c0 + ty + r) * E_ + e0 + tx] =
                __float2half_rn(tile[tx][ty + r]);
    }
}

// exact-rescue dot — VALIDATED arithmetic (R4/R6/R9-R12): ONE sequential fp32
// fmaf chain, k ascending, float4 loads. DO NOT reorder or split.
__device__ __forceinline__ float exact_logit(const float* __restrict__ xr,
                                             const float* __restrict__ wr,
                                             float cbv) {
    float acc = 0.0f;
#pragma unroll 8
    for (int k = 0; k < E_; k += 4) {
        const float4 xv = *(const float4*)(xr + k);
        const float4 wv = *(const float4*)(wr + k);
        acc = fmaf(xv.x, wv.x, acc);
        acc = fmaf(xv.y, wv.y, acc);
        acc = fmaf(xv.z, wv.z, acc);
        acc = fmaf(xv.w, wv.w, acc);
    }
    return fmaf(3.0f, acc, cbv);
}

// ---------------- kernel 2: fp16 mma.sync GEMM + fused softmax/sample -------
// Tile: BM=128, BN=128, BK=32, 3-stage. smem/stage: A (128x80B) + B (128x80B)
#define A_SZ      10240
#define STAGE_SZ  (2 * A_SZ)                // 20480
#define CS        132                       // C smem stride (floats)
#define SMEM_BYTES (128 * CS * 4)           // 67584 (>= 3*STAGE_SZ = 61440)
#define NST       (E_ / 32)                 // 16
#define SCALE_    (3.0f / 64.0f)

__device__ __forceinline__ void load_stage(uint32_t sb, int tid, int bm, int bn,
                                           int s, int buf) {
    const uint32_t stage = sb + buf * STAGE_SZ;
    const size_t kofs = (size_t)s * 32;
#pragma unroll
    for (int it = 0; it < 2; it++) {
        const int o = tid + it * 256;           // 0..511 -> 128 rows x 4 chunks
        const int row = o >> 2, ch = o & 3;
        const uint32_t dst = row * 80 + ch * 16;
        CP16(stage + dst,        g_h1 + (size_t)(bm + row) * E_ + kofs + ch * 8);
        CP16(stage + A_SZ + dst, g_h1 + (size_t)(M_ + bn + row) * E_ + kofs + ch * 8);
    }
}

__global__ __launch_bounds__(256, 2)
void gemm_fused_kernel(const float* __restrict__ b1,
                       const float* __restrict__ coff,
                       const float* __restrict__ g1,
                       const float* __restrict__ g2,
                       const float* __restrict__ w_interp,
                       const float* __restrict__ u_interp,
                       float* __restrict__ outSampled,
                       float* __restrict__ outSoft) {
    extern __shared__ char smem[];
    __shared__ float cb[128];
    const int tid  = threadIdx.x;
    const int lane = tid & 31;
    const int wid  = tid >> 5;
    const int bn   = blockIdx.x * 128;
    const int bm   = blockIdx.y * 128;
    const uint32_t sb = smem_u32(smem);

    if (tid < 128) cb[tid] = 3.0f * b1[bn + tid] + coff[bn + tid];

    // warp tiling: 2 (m) x 4 (n); warp tile m64 x n32
    const int m0 = (wid >> 2) * 64;
    const int n0 = (wid & 3) * 32;
    const int lrow = lane & 7;
    const int lmat = lane >> 3;

    float acc[4][4][4];
#pragma unroll
    for (int i = 0; i < 4; i++)
#pragma unroll
        for (int j = 0; j < 4; j++)
#pragma unroll
            for (int k = 0; k < 4; k++) acc[i][j][k] = 0.0f;

    load_stage(sb, tid, bm, bn, 0, 0); CP_COMMIT();
    load_stage(sb, tid, bm, bn, 1, 1); CP_COMMIT();

#pragma unroll 1
    for (int s = 0; s < NST; s++) {
        if (s + 2 < NST) { load_stage(sb, tid, bm, bn, s + 2, (s + 2) % 3); CP_COMMIT(); }
        if      (s < NST - 2) asm volatile("cp.async.wait_group 2;" ::: "memory");
        else if (s < NST - 1) asm volatile("cp.async.wait_group 1;" ::: "memory");
        else                  asm volatile("cp.async.wait_group 0;" ::: "memory");
        __syncthreads();

        const uint32_t stage = sb + (s % 3) * STAGE_SZ;
        const uint32_t A1 = stage;
        const uint32_t B1 = stage + A_SZ;

#pragma unroll
        for (int kk = 0; kk < 32; kk += 16) {
            uint32_t a1f[4][4], b1f[8];
#pragma unroll
            for (int mt = 0; mt < 4; mt++) {
                const int row = m0 + mt * 16 + (lmat & 1) * 8 + lrow;
                const int col = kk + (lmat >> 1) * 8;
                const uint32_t off = row * 80 + col * 2;
                ldsm_x4(a1f[mt][0], a1f[mt][1], a1f[mt][2], a1f[mt][3], A1 + off);
            }
#pragma unroll
            for (int j = 0; j < 2; j++) {
                const int row = n0 + j * 16 + (lmat >> 1) * 8 + lrow;
                const int col = kk + (lmat & 1) * 8;
                const uint32_t off = row * 80 + col * 2;
                ldsm_x4(b1f[j*4+0], b1f[j*4+1], b1f[j*4+2], b1f[j*4+3], B1 + off);
            }
#pragma unroll
            for (int mt = 0; mt < 4; mt++)
#pragma unroll
                for (int nt = 0; nt < 4; nt++) {
                    const int bb = (nt >> 1) * 4 + (nt & 1) * 2;
                    mma16816(acc[mt][nt], a1f[mt], &b1f[bb]);
                }
        }
        __syncthreads();
    }

    // ------- write accums to smem C (reuse stage memory) -------
    float* Cs = (float*)smem;
    const int crow = lane >> 2;
    const int ccol = (lane & 3) * 2;
#pragma unroll
    for (int mt = 0; mt < 4; mt++)
#pragma unroll
        for (int nt = 0; nt < 4; nt++) {
            const int r = m0 + mt * 16 + crow;
            const int c = n0 + nt * 8 + ccol;
            *(float2*)&Cs[(size_t)r * CS + c]       = make_float2(acc[mt][nt][0], acc[mt][nt][1]);
            *(float2*)&Cs[(size_t)(r + 8) * CS + c] = make_float2(acc[mt][nt][2], acc[mt][nt][3]);
        }
    __syncthreads();

    // ------- fused epilogue: softmax + provisional sample + rescue flag ------
#pragma unroll 1
    for (int rep = 0; rep < 2; rep++) {
        const int p  = rep * 256 + tid;     // 0..511
        const int tl = p >> 2;              // token local 0..127
        const int g4 = p & 3;               // group within block 0..3
        const int token = bm + tl;
        const float* cp = &Cs[(size_t)tl * CS + g4 * 32];

        float v[32];
#pragma unroll
        for (int q = 0; q < 8; q++) {
            const float4 c4 = *(const float4*)(cp + q * 4);
            v[q*4+0] = SCALE_ * c4.x + cb[g4*32 + q*4+0];
            v[q*4+1] = SCALE_ * c4.y + cb[g4*32 + q*4+1];
            v[q*4+2] = SCALE_ * c4.z + cb[g4*32 + q*4+2];
            v[q*4+3] = SCALE_ * c4.w + cb[g4*32 + q*4+3];
        }

        float mx = v[0];
#pragma unroll
        for (int i = 1; i < 32; i++) mx = fmaxf(mx, v[i]);
        float e[32], sum = 0.0f;
#pragma unroll
        for (int i = 0; i < 32; i++) { e[i] = __expf(v[i] - mx); sum += e[i]; }
        const float inv = 1.0f / sum;

        float* so = outSoft + (size_t)token * C_ + bn + g4 * 32;
#pragma unroll
        for (int q = 0; q < 8; q++)
            *(float4*)(so + q * 4) = make_float4(e[q*4+0]*inv, e[q*4+1]*inv,
                                                 e[q*4+2]*inv, e[q*4+3]*inv);

        const int gid = (bn >> 5) + g4;
        const int pair = token * G_ + gid;
        const size_t gbase = (size_t)pair * CG_;
        const float* gp1 = g1 + gbase;
        const float* gp2 = g2 + gbase;

        int a1 = 0; float t11 = -3.4e38f, t12 = -3.4e38f;
#pragma unroll
        for (int q = 0; q < 8; q++) {
            const float4 gg = *(const float4*)(gp1 + q * 4);
            const float cc[4] = {v[q*4+0] + gg.x, v[q*4+1] + gg.y,
                                 v[q*4+2] + gg.z, v[q*4+3] + gg.w};
#pragma unroll
            for (int k = 0; k < 4; k++) {
                if (cc[k] > t11) { t12 = t11; t11 = cc[k]; a1 = q*4+k; }
                else if (cc[k] > t12) { t12 = cc[k]; }
            }
        }
        int a2 = 0; float t21 = -3.4e38f, t22 = -3.4e38f;
#pragma unroll
        for (int q = 0; q < 8; q++) {
            const float4 gg = *(const float4*)(gp2 + q * 4);
            const float cc[4] = {v[q*4+0] + gg.x, v[q*4+1] + gg.y,
                                 v[q*4+2] + gg.z, v[q*4+3] + gg.w};
#pragma unroll
            for (int k = 0; k < 4; k++) {
                if (cc[k] > t21) { t22 = t21; t21 = cc[k]; a2 = q*4+k; }
                else if (cc[k] > t22) { t22 = cc[k]; }
            }
        }

        // ---- rescue flagging (same screen as validated versions) ----
        unsigned m1 = 0, m2 = 0;
        if (t11 - t12 < TAU_) {
            const float thr = t11 - 2.0f * TAU_;
#pragma unroll
            for (int i = 0; i < 32; i++)
                if (v[i] + gp1[i] >= thr) m1 |= (1u << i);
        }
        if (t21 - t22 < TAU_) {
            const float thr = t21 - 2.0f * TAU_;
#pragma unroll
            for (int i = 0; i < 32; i++)
                if (v[i] + gp2[i] >= thr) m2 |= (1u << i);
        }
        if (m1 | m2) {
            g_m1[pair] = m1;
            g_m2[pair] = m2;
            atomicOr(&g_rmask[token], 1u << gid);
        }

        const float w  = w_interp[pair];
        const float u  = u_interp[pair];
        const bool  ui = (u < 1.0f);              // INTERP_PROB = 1.0
        const float wa = ui ? w : 1.0f;
        const float wb = ui ? (1.0f - w) : 0.0f;

        float* sp = outSampled + (size_t)token * C_ + bn + g4 * 32;
#pragma unroll
        for (int q = 0; q < 8; q++) {
            float o[4];
#pragma unroll
            for (int k = 0; k < 4; k++) {
                const int i = q * 4 + k;
                float val = 0.0f;
                if (i == a1) val += wa;
                if (i == a2) val += wb;
                o[k] = val;
            }
            *(float4*)(sp + q * 4) = make_float4(o[0], o[1], o[2], o[3]);
        }
        g_idx[pair] = (unsigned)a1 | ((unsigned)a2 << 8) | (ui ? 0x10000u : 0u);
    }
}

// ---------------- kernel 3: proj + LN with INLINE warp-collective rescues ---
__global__ __launch_bounds__(128)
void proj_ln_kernel(const float* __restrict__ xg,
                    const float* __restrict__ W1g,
                    const float* __restrict__ b1,
                    const float* __restrict__ coff,
                    const float* __restrict__ g1,
                    const float* __restrict__ g2,
                    const float* __restrict__ w_interp,
                    const float* __restrict__ b2,
                    const float* __restrict__ gamma,
                    const float* __restrict__ beta,
                    float* __restrict__ outSampled,
                    float* __restrict__ outPos,
                    float* __restrict__ outNeg) {
    const int tok = blockIdx.x;
    const int tid = threadIdx.x;   // 128 threads, 4 e's each
    const int lane = tid & 31;
    const int wz   = tid >> 5;
    __shared__ unsigned sidx[32];
    __shared__ float    sw[32];
    __shared__ float    red1[4], red2[4];

    if (tid < 32) {
        sidx[tid] = g_idx[(size_t)tok * G_ + tid];
        sw[tid]   = w_interp[(size_t)tok * G_ + tid];
    }
    __syncthreads();

    // ---- inline rescues (block-uniform branch; warp j handles j-th set bit mod 4)
    const unsigned rmask = g_rmask[tok];
    if (rmask) {
        const float* xr = xg + (size_t)tok * E_;
        unsigned mm = rmask;
        int j = 0;
        while (mm) {
            const int gid = __ffs(mm) - 1;
            mm &= mm - 1;
            if ((j & 3) == wz) {
                const int pair = tok * G_ + gid;
                const unsigned m1 = g_m1[pair], m2 = g_m2[pair];
                const unsigned packed = sidx[gid];
                int a1 = packed & 255, a2 = (packed >> 8) & 255;
                const bool ui = (packed & 0x10000u) != 0u;

                const bool need1 = (m1 >> lane) & 1u;
                const bool need2 = (m2 >> lane) & 1u;
                float cand1 = -3.4e38f, cand2 = -3.4e38f;
                if (need1 || need2) {
                    const int c = gid * CG_ + lane;
                    const float cbv = 3.0f * b1[c] + coff[c];
                    const float vex = exact_logit(xr, W1g + (size_t)c * E_, cbv);
                    if (need1) cand1 = vex + g1[(size_t)pair * CG_ + lane];
                    if (need2) cand2 = vex + g2[(size_t)pair * CG_ + lane];
                }
                // warp argmax; tie -> lower index (== sequential strict-> first max)
                int i1 = lane, i2 = lane;
#pragma unroll
                for (int off = 16; off > 0; off >>= 1) {
                    const float ov1 = __shfl_xor_sync(0xFFFFFFFFu, cand1, off);
                    const int   oi1 = __shfl_xor_sync(0xFFFFFFFFu, i1, off);
                    if (ov1 > cand1 || (ov1 == cand1 && oi1 < i1)) { cand1 = ov1; i1 = oi1; }
                    const float ov2 = __shfl_xor_sync(0xFFFFFFFFu, cand2, off);
                    const int   oi2 = __shfl_xor_sync(0xFFFFFFFFu, i2, off);
                    if (ov2 > cand2 || (ov2 == cand2 && oi2 < i2)) { cand2 = ov2; i2 = oi2; }
                }
                if (m1) a1 = i1;
                if (m2) a2 = i2;

                const float w  = sw[gid];
                const float wa = ui ? w : 1.0f;
                const float wb = ui ? (1.0f - w) : 0.0f;
                float* sp = outSampled + (size_t)tok * C_ + gid * CG_;
                float val = 0.0f;
                if (lane == a1) val += wa;
                if (lane == a2) val += wb;
                sp[lane] = val;                        // coalesced patch
                if (lane == 0)
                    sidx[gid] = (unsigned)a1 | ((unsigned)a2 << 8) | (ui ? 0x10000u : 0u);
            }
            j++;
        }
        __syncthreads();                               // block-uniform branch: legal
    }

    const int e4 = tid * 4;
    float4 bb = *(const float4*)(b2 + e4);
    float hx = bb.x, hy = bb.y, hz = bb.z, hw = bb.w;

#pragma unroll
    for (int g = 0; g < 32; g++) {
        const unsigned p = sidx[g];
        const float w = sw[g];
        const bool ui = (p & 0x10000u) != 0u;
        const int a1 = p & 255;
        const int a2 = (p >> 8) & 255;
        const float wa = ui ? w : 1.0f;
        const float wb = ui ? (1.0f - w) : 0.0f;
        const uint2 u1 = *(const uint2*)&g_W2h[(size_t)(g * CG_ + a1) * E_ + e4];
        const uint2 u2 = *(const uint2*)&g_W2h[(size_t)(g * CG_ + a2) * E_ + e4];
        const float2 r1a = __half22float2(*(const __half2*)&u1.x);
        const float2 r1b = __half22float2(*(const __half2*)&u1.y);
        const float2 r2a = __half22float2(*(const __half2*)&u2.x);
        const float2 r2b = __half22float2(*(const __half2*)&u2.y);
        hx += wa * r1a.x + wb * r2a.x;
        hy += wa * r1a.y + wb * r2a.y;
        hz += wa * r1b.x + wb * r2b.x;
        hw += wa * r1b.y + wb * r2b.y;
    }

    float s1 = hx + hy + hz + hw;
    float s2 = hx * hx + hy * hy + hz * hz + hw * hw;
#pragma unroll
    for (int off = 16; off > 0; off >>= 1) {
        s1 += __shfl_xor_sync(0xFFFFFFFFu, s1, off);
        s2 += __shfl_xor_sync(0xFFFFFFFFu, s2, off);
    }
    if (lane == 0) { red1[wz] = s1; red2[wz] = s2; }
    __syncthreads();
    s1 = red1[0] + red1[1] + red1[2] + red1[3];
    s2 = red2[0] + red2[1] + red2[2] + red2[3];

    const float mean = s1 * (1.0f / (float)E_);
    const float var  = s2 * (1.0f / (float)E_) - mean * mean;
    const float rstd = rsqrtf(var + 1e-5f);

    const float4 gm = *(const float4*)(gamma + e4);
    const float4 bt = *(const float4*)(beta + e4);
    float4 o;
    o.x = (hx - mean) * rstd * gm.x + bt.x;
    o.y = (hy - mean) * rstd * gm.y + bt.y;
    o.z = (hz - mean) * rstd * gm.z + bt.z;
    o.w = (hw - mean) * rstd * gm.w + bt.w;

    *(float4*)(outPos + (size_t)tok * E_ + e4) = o;
    *(float4*)(outNeg + (size_t)tok * E_ + e4) = o;   // rev fwd == sampled
}

// ---------------- launch ----------------
extern "C" void kernel_launch(void* const* d_in, const int* in_sizes, int n_in,
                              void* d_out, int out_size) {
    const float* x     = (const float*)d_in[0];
    const float* W1    = (const float*)d_in[1];
    const float* b1    = (const float*)d_in[2];
    const float* coff  = (const float*)d_in[3];
    const float* W2    = (const float*)d_in[4];
    const float* b2    = (const float*)d_in[5];
    const float* gamma = (const float*)d_in[6];
    const float* beta  = (const float*)d_in[7];
    const float* g1    = (const float*)d_in[8];
    const float* g2    = (const float*)d_in[9];
    const float* wi    = (const float*)d_in[10];
    const float* ui    = (const float*)d_in[11];

    float* out        = (float*)d_out;
    float* outSampled = out;
    float* outSoft    = out + (size_t)M_ * C_;
    float* outPos     = out + 2 * (size_t)M_ * C_;
    float* outNeg     = outPos + (size_t)M_ * E_;

    cudaFuncSetAttribute(gemm_fused_kernel,
                         cudaFuncAttributeMaxDynamicSharedMemorySize, SMEM_BYTES);

    prep_kernel<<<SPLIT_BLOCKS + 512, 256>>>(x, W1, W2);
    gemm_fused_kernel<<<dim3(C_ / 128, M_ / 128), 256, SMEM_BYTES>>>(
        b1, coff, g1, g2, wi, ui, outSampled, outSoft);
    proj_ln_kernel<<<M_, 128>>>(x, W1, b1, coff, g1, g2, wi,
                                b2, gamma, beta, outSampled, outPos, outNeg);
}